// round 14
// baseline (speedup 1.0000x reference)
#include <cuda_runtime.h>
#include <cstdint>

typedef unsigned long long u64;

#define Bn 1024
#define Tn 512
#define Ln 64
#define Nn 8
#define Hn 128
#define H2P 130             /* padded float2 row for h2 buffers (bank-spread) */
#define DIn 32
#define DOn 16
#define RROWS 8
#define PAIRS 4
#define NCTA (Bn / RROWS)   /* 128 */
#define NTHR 256
#define XFULL ((size_t)Bn * Tn * DOn)

// z-path scratch: [t][cta][pair][l] as packed float2 (u64). 128 MB.
__device__ u64 zbuf[(size_t)Tn * NCTA * PAIRS * Ln];

// ---------------- scan-kernel shared memory (~224 KB) ------------------------
struct __align__(16) Smem {
    float fW1t[Hn][68];    // f_W1 z-part transposed [j][k]; 68 == 4 (mod 32)
    float fW2t[Hn][132];   // f_W2 transposed; 132 == 4 (mod 32)
    float gW1t[Hn][68];
    float gW2t[Hn][132];
    float2 z2[PAIRS][Ln];  // state, row-pairs packed: .x = row 2p, .y = row 2p+1
    float2 h1f[PAIRS][Hn];
    float2 h2f[PAIRS][H2P]; // padded: ph3 reads 4 distinct pairs per lane-quad
    float2 h1g[PAIRS][Hn];
    float2 h2g[PAIRS][H2P];
    float2 dws[PAIRS][Nn];
};

// ---------------- f32x2 packed helpers ---------------------------------------
__device__ __forceinline__ u64 dup2f(float v) {
    u64 r; asm("mov.b64 %0,{%1,%1};" : "=l"(r) : "f"(v)); return r;
}
__device__ __forceinline__ u64 pk2(float lo, float hi) {
    u64 r; asm("mov.b64 %0,{%1,%2};" : "=l"(r) : "f"(lo), "f"(hi)); return r;
}
__device__ __forceinline__ void unpk2(u64 v, float& lo, float& hi) {
    asm("mov.b64 {%0,%1},%2;" : "=f"(lo), "=f"(hi) : "l"(v));
}
__device__ __forceinline__ u64 f2fma(u64 a, u64 b, u64 c) {
    u64 d; asm("fma.rn.f32x2 %0,%1,%2,%3;" : "=l"(d) : "l"(a), "l"(b), "l"(c)); return d;
}
__device__ __forceinline__ u64 f2add(u64 a, u64 b) {
    u64 d; asm("add.rn.f32x2 %0,%1,%2;" : "=l"(d) : "l"(a), "l"(b)); return d;
}

// softplus(x) = max(x,0) + log1p(exp(-|x|))
__device__ __forceinline__ float softplus1(float x) {
    float e = __expf(-fabsf(x));
    return fmaxf(x, 0.f) + 0.69314718055994531f * __log2f(1.f + e);
}
// tanh(x) = 1 - 2/(exp(2x)+1)
__device__ __forceinline__ float tanh1(float x) {
    float e = __expf(2.f * x);
    return 1.f - __fdividef(2.f, e + 1.f);
}
__device__ __forceinline__ u64 tanh2(u64 v) {
    float lo, hi; unpk2(v, lo, hi);
    return pk2(tanh1(lo), tanh1(hi));
}

// ---------------- main persistent scan kernel --------------------------------
__global__ void __launch_bounds__(NTHR, 1)
sde_scan_kernel(const float* __restrict__ init_noise, const float* __restrict__ dw_noise,
                const float* __restrict__ ts,   const float* __restrict__ embW,
                const float* __restrict__ embb, const float* __restrict__ fW1,
                const float* __restrict__ fb1,  const float* __restrict__ fW2,
                const float* __restrict__ fb2,  const float* __restrict__ fW3,
                const float* __restrict__ fb3,  const float* __restrict__ gW1,
                const float* __restrict__ gb1,  const float* __restrict__ gW2,
                const float* __restrict__ gb2,  const float* __restrict__ gW3,
                const float* __restrict__ gb3)
{
    extern __shared__ __align__(16) char smraw[];
    Smem& sm = *reinterpret_cast<Smem*>(smraw);
    const int tid = threadIdx.x;
    const int wg = tid & 127;            // layer neuron
    const int team = tid >> 7;           // 0,1
    const int p0 = 2 * team;             // team's pairs (ph1/ph2)
    const int rowbase = blockIdx.x * RROWS;

    // ---- stage SMEM-resident weights (team-split) ----
    {
        const int j = wg;
        if (team == 0) {
#pragma unroll 4
            for (int k = 0; k < Ln; k++) sm.fW1t[j][k] = fW1[(k + 1) * Hn + j];
#pragma unroll 4
            for (int k = 0; k < Hn; k++) sm.fW2t[j][k] = fW2[k * Hn + j];
        } else {
#pragma unroll 4
            for (int k = 0; k < Ln; k++) sm.gW1t[j][k] = gW1[(k + 1) * Hn + j];
#pragma unroll 4
            for (int k = 0; k < Hn; k++) sm.gW2t[j][k] = gW2[k * Hn + j];
        }
    }

    // ---- per-thread register params ----
    const float w10f = __ldg(fW1 + wg), w10g = __ldg(gW1 + wg);
    const float bf1 = __ldg(fb1 + wg), bf2 = __ldg(fb2 + wg);
    const float bg1 = __ldg(gb1 + wg), bg2 = __ldg(gb2 + wg);
    // ph3 mapping: thread owns (pair qq, latent lq) for f3 + z-update,
    // and g3 outputs {2tid, 2tid+1} (l = tid>>2 = lq, n = (tid&3)*2 = 2qq)
    const int lq = tid >> 2, qq = tid & 3;
    const float bf3v = __ldg(fb3 + lq);
    const float2 bg3v = *(const float2*)(gb3 + 2 * tid);

    // ---- z0 = init_noise @ emb_W + emb_b; store to zbuf[t=0] ----
    {
        int l = tid & 63, p = tid >> 6;
        float ax = __ldg(embb + l), ay = ax;
#pragma unroll 4
        for (int i = 0; i < DIn; i++) {
            float w = embW[i * Ln + l];
            ax = fmaf(init_noise[(rowbase + 2 * p) * DIn + i], w, ax);
            ay = fmaf(init_noise[(rowbase + 2 * p + 1) * DIn + i], w, ay);
        }
        sm.z2[p][l] = make_float2(ax, ay);
        zbuf[(size_t)blockIdx.x * (PAIRS * Ln) + tid] = *(const u64*)&sm.z2[p][l];
    }
    __syncthreads();

    // ---- 511 Euler-Maruyama steps, 3 barriers each --------------------------
    for (int s = 0; s < Tn - 1; s++) {
        const float tcur = __ldg(ts + s);
        const float dt = __ldg(ts + s + 1) - tcur;
        const float sq = sqrtf(dt);
        if (tid < 32) {   // Brownian increments (consumed in ph3, 2 bars later)
            int p = tid >> 3, n = tid & 7;
            const float* dwp = dw_noise + ((size_t)s * Bn + rowbase + 2 * p) * Nn + n;
            sm.dws[p][n] = make_float2(dwp[0] * sq, dwp[Nn] * sq);
        }

        // ===== ph1: f layer1 + g layer1 (shared z2 act loads, 8 chains) =====
        {
            u64 z0 = dup2f(0.f);
            u64 fi = dup2f(fmaf(w10f, tcur, bf1));
            u64 gi = dup2f(fmaf(w10g, tcur, bg1));
            u64 fA[2] = { fi, fi }, fB[2] = { z0, z0 };
            u64 gA[2] = { gi, gi }, gB[2] = { z0, z0 };
#pragma unroll 4
            for (int c = 0; c < Ln / 4; c++) {
                float4 wf = *(const float4*)&sm.fW1t[wg][4 * c];
                float4 wgv = *(const float4*)&sm.gW1t[wg][4 * c];
                u64 f0 = dup2f(wf.x), f1 = dup2f(wf.y), f2 = dup2f(wf.z), f3 = dup2f(wf.w);
                u64 g0 = dup2f(wgv.x), g1 = dup2f(wgv.y), g2 = dup2f(wgv.z), g3 = dup2f(wgv.w);
#pragma unroll
                for (int e = 0; e < 2; e++) {
                    ulonglong2 x0 = *(const ulonglong2*)&sm.z2[p0 + e][4 * c];
                    ulonglong2 x1 = *(const ulonglong2*)&sm.z2[p0 + e][4 * c + 2];
                    fA[e] = f2fma(f0, x0.x, fA[e]);
                    fB[e] = f2fma(f1, x0.y, fB[e]);
                    fA[e] = f2fma(f2, x1.x, fA[e]);
                    fB[e] = f2fma(f3, x1.y, fB[e]);
                    gA[e] = f2fma(g0, x0.x, gA[e]);
                    gB[e] = f2fma(g1, x0.y, gB[e]);
                    gA[e] = f2fma(g2, x1.x, gA[e]);
                    gB[e] = f2fma(g3, x1.y, gB[e]);
                }
            }
#pragma unroll
            for (int e = 0; e < 2; e++) {
                u64 tf = f2add(fA[e], fB[e]);
                u64 tg = f2add(gA[e], gB[e]);
                float lo, hi;
                unpk2(tf, lo, hi);
                sm.h1f[p0 + e][wg] = make_float2(softplus1(lo), softplus1(hi));
                unpk2(tg, lo, hi);
                sm.h1g[p0 + e][wg] = make_float2(softplus1(lo), softplus1(hi));
            }
        }
        __syncthreads();

        // ===== ph2: f layer2 + g layer2 =====
        {
            u64 z0 = dup2f(0.f);
            u64 fi = dup2f(bf2), gi = dup2f(bg2);
            u64 fA[2] = { fi, fi }, fB[2] = { z0, z0 };
            u64 gA[2] = { gi, gi }, gB[2] = { z0, z0 };
#pragma unroll 4
            for (int c = 0; c < Hn / 4; c++) {
                float4 wf = *(const float4*)&sm.fW2t[wg][4 * c];
                float4 wgv = *(const float4*)&sm.gW2t[wg][4 * c];
                u64 f0 = dup2f(wf.x), f1 = dup2f(wf.y), f2 = dup2f(wf.z), f3 = dup2f(wf.w);
                u64 g0 = dup2f(wgv.x), g1 = dup2f(wgv.y), g2 = dup2f(wgv.z), g3 = dup2f(wgv.w);
#pragma unroll
                for (int e = 0; e < 2; e++) {
                    ulonglong2 xf0 = *(const ulonglong2*)&sm.h1f[p0 + e][4 * c];
                    ulonglong2 xf1 = *(const ulonglong2*)&sm.h1f[p0 + e][4 * c + 2];
                    fA[e] = f2fma(f0, xf0.x, fA[e]);
                    fB[e] = f2fma(f1, xf0.y, fB[e]);
                    fA[e] = f2fma(f2, xf1.x, fA[e]);
                    fB[e] = f2fma(f3, xf1.y, fB[e]);
                    ulonglong2 xg0 = *(const ulonglong2*)&sm.h1g[p0 + e][4 * c];
                    ulonglong2 xg1 = *(const ulonglong2*)&sm.h1g[p0 + e][4 * c + 2];
                    gA[e] = f2fma(g0, xg0.x, gA[e]);
                    gB[e] = f2fma(g1, xg0.y, gB[e]);
                    gA[e] = f2fma(g2, xg1.x, gA[e]);
                    gB[e] = f2fma(g3, xg1.y, gB[e]);
                }
            }
#pragma unroll
            for (int e = 0; e < 2; e++) {
                u64 tf = f2add(fA[e], fB[e]);
                u64 tg = f2add(gA[e], gB[e]);
                float lo, hi;
                unpk2(tf, lo, hi);
                sm.h2f[p0 + e][wg] = make_float2(softplus1(lo), softplus1(hi));
                unpk2(tg, lo, hi);
                sm.h2g[p0 + e][wg] = make_float2(softplus1(lo), softplus1(hi));
            }
        }
        __syncthreads();

        // ===== ph3: f3 + g3 + einsum + FUSED z-update (no ph4, no fo/geo SMEM) =====
        {
            const u64 one2 = dup2f(1.f);
            // f3: pair qq, output lq (register result)
            u64 a0 = dup2f(bf3v), a1 = dup2f(0.f);
            const float* fp = fW3 + lq;
            // g3: outputs {2tid, 2tid+1}, all 4 pairs; gW3 read once per CTA
            u64 acc[PAIRS][2];
#pragma unroll
            for (int p = 0; p < PAIRS; p++) {
                acc[p][0] = dup2f(bg3v.x);
                acc[p][1] = dup2f(bg3v.y);
            }
            const float2* g2 = reinterpret_cast<const float2*>(gW3) + tid;
#pragma unroll 4
            for (int c = 0; c < Hn / 2; c++) {
                // f3: k = 2c, 2c+1 (h2f padded to 130 -> quad-q reads conflict-free)
                u64 w0 = dup2f(__ldg(fp + (2 * c) * Ln));
                u64 w1 = dup2f(__ldg(fp + (2 * c + 1) * Ln));
                a0 = f2fma(w0, *(const u64*)&sm.h2f[qq][2 * c], a0);
                a1 = f2fma(w1, *(const u64*)&sm.h2f[qq][2 * c + 1], a1);
                // g3: k-rows 2c, 2c+1 (LDG.64, fully coalesced over warp)
                float2 va = __ldg(g2 + (size_t)(2 * c) * (Ln * Nn / 2));
                float2 vb = __ldg(g2 + (size_t)(2 * c + 1) * (Ln * Nn / 2));
                u64 wa0 = dup2f(va.x), wa1 = dup2f(va.y);
                u64 wb0 = dup2f(vb.x), wb1 = dup2f(vb.y);
#pragma unroll
                for (int p = 0; p < PAIRS; p++) {
                    ulonglong2 h = *(const ulonglong2*)&sm.h2g[p][2 * c];
                    acc[p][0] = f2fma(wa0, h.x, acc[p][0]);
                    acc[p][1] = f2fma(wa1, h.x, acc[p][1]);
                    acc[p][0] = f2fma(wb0, h.y, acc[p][0]);
                    acc[p][1] = f2fma(wb1, h.y, acc[p][1]);
                }
            }
            // einsum partials: n's = 2qq, 2qq+1; quad shfl gives FULL n-sum on all lanes
            const int nb = 2 * qq;
            u64 pa[PAIRS];
#pragma unroll
            for (int p = 0; p < PAIRS; p++) {
                u64 t0 = tanh2(acc[p][0]);
                u64 t1 = tanh2(acc[p][1]);
                u64 v = f2fma(t0, *(const u64*)&sm.dws[p][nb], dup2f(0.f));
                v = f2fma(t1, *(const u64*)&sm.dws[p][nb + 1], v);
                v = f2fma(one2, __shfl_xor_sync(0xffffffffu, v, 1), v);
                v = f2fma(one2, __shfl_xor_sync(0xffffffffu, v, 2), v);
                pa[p] = v;
            }
            u64 geo = (qq == 0) ? pa[0] : (qq == 1) ? pa[1] : (qq == 2) ? pa[2] : pa[3];
            // f3 finish (registers only) + z update for (qq, lq)
            u64 fv = tanh2(f2add(a0, a1));
            u64 z = *(const u64*)&sm.z2[qq][lq];
            z = f2fma(fv, dup2f(dt), z);
            z = f2fma(one2, geo, z);
            *(u64*)&sm.z2[qq][lq] = z;
            zbuf[((size_t)(s + 1) * NCTA + blockIdx.x) * (PAIRS * Ln)
                 + qq * Ln + lq] = z;
        }
        __syncthreads();
    }
}

// ---------------- readout kernel: x = relu(z@rW1+b1)@rW2+b2 ------------------
#define RO_TS 32   /* time steps per block */
struct __align__(16) RoSmem {
    float rw1t[Hn][68];     // rW1 transposed [j][l]
    float w2t[DOn][130];    // rW2 transposed [d][k], pad 130
    float2 zt[PAIRS][Ln];   // current z tile (2 KB)
    float h1T[RROWS][132];  // stage-1 output, scalar per row, pad 132
};

__global__ void __launch_bounds__(256, 4)
readout_kernel(const float* __restrict__ rW1, const float* __restrict__ rb1,
               const float* __restrict__ rW2, const float* __restrict__ rb2,
               float* __restrict__ out)
{
    extern __shared__ __align__(16) char smraw[];
    RoSmem& sm = *reinterpret_cast<RoSmem*>(smraw);
    const int tid = threadIdx.x;
    const int cta = blockIdx.x & (NCTA - 1);
    const int slice = blockIdx.x >> 7;
    const int rowbase = cta * RROWS;

    // stage rW1 transposed: [j][l], coalesced LDG over j
    {
        const int jj = tid & 127, half = tid >> 7;
#pragma unroll 4
        for (int l = half * 32; l < half * 32 + 32; l++)
            sm.rw1t[jj][l] = rW1[l * Hn + jj];
    }
    // stage rW2 transposed: [d][k]
    for (int i = tid; i < Hn * DOn; i += 256) {
        int d = i & 15, k = i >> 4;
        sm.w2t[d][k] = rW2[i];
    }
    const float rb1v = __ldg(rb1 + (tid & 127));
    const int jr = tid & 127, p0 = (tid >> 7) * 2;             // stage-1 mapping
    const int row2 = tid >> 5, kh5 = (tid >> 4) & 1, d5 = tid & 15;  // stage-2
    const float rb2v = __ldg(rb2 + d5);
    __syncthreads();

    for (int it = 0; it < RO_TS; it++) {
        const int t = slice * RO_TS + it;
        // load z tile
        ((u64*)&sm.zt[0][0])[tid] =
            zbuf[((size_t)t * NCTA + cta) * (PAIRS * Ln) + tid];
        __syncthreads();
        // stage 1: h = relu(z @ rW1 + b1); thread = (jr, 2 pairs); write h1T
        {
            u64 aA[2], aB[2];
            u64 bi = dup2f(rb1v), z0 = dup2f(0.f);
            aA[0] = bi; aA[1] = bi; aB[0] = z0; aB[1] = z0;
#pragma unroll 4
            for (int c = 0; c < Ln / 4; c++) {
                float4 w = *(const float4*)&sm.rw1t[jr][4 * c];
                u64 w0 = dup2f(w.x), w1 = dup2f(w.y), w2 = dup2f(w.z), w3 = dup2f(w.w);
#pragma unroll
                for (int e = 0; e < 2; e++) {
                    ulonglong2 x0 = *(const ulonglong2*)&sm.zt[p0 + e][4 * c];
                    ulonglong2 x1 = *(const ulonglong2*)&sm.zt[p0 + e][4 * c + 2];
                    aA[e] = f2fma(w0, x0.x, aA[e]);
                    aB[e] = f2fma(w1, x0.y, aB[e]);
                    aA[e] = f2fma(w2, x1.x, aA[e]);
                    aB[e] = f2fma(w3, x1.y, aB[e]);
                }
            }
#pragma unroll
            for (int e = 0; e < 2; e++) {
                u64 tv = f2add(aA[e], aB[e]);
                float lo, hi; unpk2(tv, lo, hi);
                sm.h1T[2 * (p0 + e)][jr]     = fmaxf(lo, 0.f);
                sm.h1T[2 * (p0 + e) + 1][jr] = fmaxf(hi, 0.f);
            }
        }
        __syncthreads();
        // stage 2: x = h @ rW2 + b2; thread = (row2, kh5, d5), f32x2 over k-pairs
        {
            u64 acc = dup2f(0.f);
            const float* hT = &sm.h1T[row2][kh5 * 64];
            const float* wT = &sm.w2t[d5][kh5 * 64];
#pragma unroll 8
            for (int kk = 0; kk < 64; kk += 2)
                acc = f2fma(*(const u64*)&hT[kk], *(const u64*)&wT[kk], acc);
            float lo, hi; unpk2(acc, lo, hi);
            float a = lo + hi;
            a += __shfl_xor_sync(0xffffffffu, a, 16);
            if (kh5 == 0) {
                a += rb2v;
                size_t row = (size_t)rowbase + row2;
                out[(row * Tn + t) * DOn + d5] = a;
                if ((t & 7) == 0)
                    out[XFULL + (row * (Tn / 8) + (t >> 3)) * DOn + d5] = a;
            }
        }
        __syncthreads();
    }
}

extern "C" void kernel_launch(void* const* d_in, const int* in_sizes, int n_in,
                              void* d_out, int out_size) {
    (void)in_sizes; (void)n_in; (void)out_size;
    cudaFuncSetAttribute(sde_scan_kernel, cudaFuncAttributeMaxDynamicSharedMemorySize,
                         (int)sizeof(Smem));
    cudaFuncSetAttribute(readout_kernel, cudaFuncAttributeMaxDynamicSharedMemorySize,
                         (int)sizeof(RoSmem));
    sde_scan_kernel<<<NCTA, NTHR, sizeof(Smem)>>>(
        (const float*)d_in[0],  (const float*)d_in[1],  (const float*)d_in[2],
        (const float*)d_in[3],  (const float*)d_in[4],  (const float*)d_in[5],
        (const float*)d_in[6],  (const float*)d_in[7],  (const float*)d_in[8],
        (const float*)d_in[9],  (const float*)d_in[10], (const float*)d_in[11],
        (const float*)d_in[12], (const float*)d_in[13], (const float*)d_in[14],
        (const float*)d_in[15], (const float*)d_in[16]);
    readout_kernel<<<NCTA * (Tn / RO_TS), 256, sizeof(RoSmem)>>>(
        (const float*)d_in[17], (const float*)d_in[18],
        (const float*)d_in[19], (const float*)d_in[20],
        (float*)d_out);
}

// round 15
// speedup vs baseline: 1.0156x; 1.0156x over previous
#include <cuda_runtime.h>
#include <cstdint>

typedef unsigned long long u64;

#define Bn 1024
#define Tn 512
#define Ln 64
#define Nn 8
#define Hn 128
#define DIn 32
#define DOn 16
#define RROWS 8
#define PAIRS 4
#define NCTA (Bn / RROWS)   /* 128 */
#define NTHR 256
#define XFULL ((size_t)Bn * Tn * DOn)

// z-path scratch: [t][cta][pair][l] as packed float2 (u64). 128 MB.
__device__ u64 zbuf[(size_t)Tn * NCTA * PAIRS * Ln];

// ---------------- scan-kernel shared memory (~225 KB) ------------------------
struct __align__(16) Smem {
    float fW1t[Hn][68];    // f_W1 z-part transposed [j][k]; 68 == 4 (mod 32)
    float fW2t[Hn][132];   // f_W2 transposed; 132 == 4 (mod 32)
    float gW1t[Hn][68];
    float gW2t[Hn][132];
    float2 z2[PAIRS][Ln];  // state, row-pairs packed: .x = row 2p, .y = row 2p+1
    float2 h1f[PAIRS][Hn];
    float2 h2f[PAIRS][Hn];
    float2 h1g[PAIRS][Hn];
    float2 h2g[PAIRS][Hn];
    float2 foT[PAIRS][Ln]; // drift outputs (team-local halves)
    float2 dws[PAIRS][Nn];
};

// ---------------- f32x2 packed helpers ---------------------------------------
__device__ __forceinline__ u64 dup2f(float v) {
    u64 r; asm("mov.b64 %0,{%1,%1};" : "=l"(r) : "f"(v)); return r;
}
__device__ __forceinline__ u64 pk2(float lo, float hi) {
    u64 r; asm("mov.b64 %0,{%1,%2};" : "=l"(r) : "f"(lo), "f"(hi)); return r;
}
__device__ __forceinline__ void unpk2(u64 v, float& lo, float& hi) {
    asm("mov.b64 {%0,%1},%2;" : "=f"(lo), "=f"(hi) : "l"(v));
}
__device__ __forceinline__ u64 f2fma(u64 a, u64 b, u64 c) {
    u64 d; asm("fma.rn.f32x2 %0,%1,%2,%3;" : "=l"(d) : "l"(a), "l"(b), "l"(c)); return d;
}
__device__ __forceinline__ u64 f2add(u64 a, u64 b) {
    u64 d; asm("add.rn.f32x2 %0,%1,%2;" : "=l"(d) : "l"(a), "l"(b)); return d;
}
// team-scoped named barrier (128 threads each)
__device__ __forceinline__ void tbar(int team) {
    asm volatile("bar.sync %0, %1;" :: "r"(team + 1), "r"(128) : "memory");
}

// softplus(x) = max(x,0) + log1p(exp(-|x|))
__device__ __forceinline__ float softplus1(float x) {
    float e = __expf(-fabsf(x));
    return fmaxf(x, 0.f) + 0.69314718055994531f * __log2f(1.f + e);
}
// tanh(x) = 1 - 2/(exp(2x)+1)
__device__ __forceinline__ float tanh1(float x) {
    float e = __expf(2.f * x);
    return 1.f - __fdividef(2.f, e + 1.f);
}
__device__ __forceinline__ u64 tanh2(u64 v) {
    float lo, hi; unpk2(v, lo, hi);
    return pk2(tanh1(lo), tanh1(hi));
}

// ---------------- main persistent scan kernel --------------------------------
__global__ void __launch_bounds__(NTHR, 1)
sde_scan_kernel(const float* __restrict__ init_noise, const float* __restrict__ dw_noise,
                const float* __restrict__ ts,   const float* __restrict__ embW,
                const float* __restrict__ embb, const float* __restrict__ fW1,
                const float* __restrict__ fb1,  const float* __restrict__ fW2,
                const float* __restrict__ fb2,  const float* __restrict__ fW3,
                const float* __restrict__ fb3,  const float* __restrict__ gW1,
                const float* __restrict__ gb1,  const float* __restrict__ gW2,
                const float* __restrict__ gb2,  const float* __restrict__ gW3,
                const float* __restrict__ gb3)
{
    extern __shared__ __align__(16) char smraw[];
    Smem& sm = *reinterpret_cast<Smem*>(smraw);
    const int tid = threadIdx.x;
    const int idx = tid & 127;           // index within team
    const int team = tid >> 7;           // 0,1
    const int p0 = 2 * team;             // team's pairs p0, p0+1
    const int rowbase = blockIdx.x * RROWS;

    // ---- stage SMEM-resident weights (team-split staging; used by BOTH teams) ----
    {
        const int j = idx;
        if (team == 0) {
#pragma unroll 4
            for (int k = 0; k < Ln; k++) sm.fW1t[j][k] = fW1[(k + 1) * Hn + j];
#pragma unroll 4
            for (int k = 0; k < Hn; k++) sm.fW2t[j][k] = fW2[k * Hn + j];
        } else {
#pragma unroll 4
            for (int k = 0; k < Ln; k++) sm.gW1t[j][k] = gW1[(k + 1) * Hn + j];
#pragma unroll 4
            for (int k = 0; k < Hn; k++) sm.gW2t[j][k] = gW2[k * Hn + j];
        }
    }

    // ---- per-thread register params ----
    const float w10f = __ldg(fW1 + idx), w10g = __ldg(gW1 + idx);
    const float bf1 = __ldg(fb1 + idx), bf2 = __ldg(fb2 + idx);
    const float bg1 = __ldg(gb1 + idx), bg2 = __ldg(gb2 + idx);
    // ph3 mappings (team-local)
    const int lf = idx & 63, qf = p0 + (idx >> 6);     // f3: (pair qf, latent lf)
    const float bf3v = __ldg(fb3 + lf);
    float bg3a[4];                                      // g3 outputs 4idx..4idx+3
#pragma unroll
    for (int i = 0; i < 4; i++) bg3a[i] = __ldg(gb3 + 4 * idx + i);
    const int lz = idx >> 1, ez = idx & 1;              // z-update: pair p0+ez, l=lz

    // ---- z0 = init_noise @ emb_W + emb_b; store to zbuf[t=0] ----
    {
        int l = tid & 63, p = tid >> 6;
        float ax = __ldg(embb + l), ay = ax;
#pragma unroll 4
        for (int i = 0; i < DIn; i++) {
            float w = embW[i * Ln + l];
            ax = fmaf(init_noise[(rowbase + 2 * p) * DIn + i], w, ax);
            ay = fmaf(init_noise[(rowbase + 2 * p + 1) * DIn + i], w, ay);
        }
        sm.z2[p][l] = make_float2(ax, ay);
        zbuf[(size_t)blockIdx.x * (PAIRS * Ln) + tid] = *(const u64*)&sm.z2[p][l];
    }
    __syncthreads();   // weights + z0 visible to both teams; teams decouple after this

    // ---- 511 Euler-Maruyama steps; teams fully independent (named barriers) ----
    for (int s = 0; s < Tn - 1; s++) {
        const float tcur = __ldg(ts + s);
        const float dt = __ldg(ts + s + 1) - tcur;
        const float sq = sqrtf(dt);
        if (idx < 16) {   // team's own Brownian increments (consumed in ph3)
            int p = p0 + (idx >> 3), n = idx & 7;
            const float* dwp = dw_noise + ((size_t)s * Bn + rowbase + 2 * p) * Nn + n;
            sm.dws[p][n] = make_float2(dwp[0] * sq, dwp[Nn] * sq);
        }

        // ===== ph1: f layer1 + g layer1 for team's 2 pairs =====
        {
            u64 z0 = dup2f(0.f);
            u64 fi = dup2f(fmaf(w10f, tcur, bf1));
            u64 gi = dup2f(fmaf(w10g, tcur, bg1));
            u64 fA[2] = { fi, fi }, fB[2] = { z0, z0 };
            u64 gA[2] = { gi, gi }, gB[2] = { z0, z0 };
#pragma unroll 4
            for (int c = 0; c < Ln / 4; c++) {
                float4 wf = *(const float4*)&sm.fW1t[idx][4 * c];
                float4 wgv = *(const float4*)&sm.gW1t[idx][4 * c];
                u64 f0 = dup2f(wf.x), f1 = dup2f(wf.y), f2 = dup2f(wf.z), f3 = dup2f(wf.w);
                u64 g0 = dup2f(wgv.x), g1 = dup2f(wgv.y), g2 = dup2f(wgv.z), g3 = dup2f(wgv.w);
#pragma unroll
                for (int e = 0; e < 2; e++) {
                    ulonglong2 x0 = *(const ulonglong2*)&sm.z2[p0 + e][4 * c];
                    ulonglong2 x1 = *(const ulonglong2*)&sm.z2[p0 + e][4 * c + 2];
                    fA[e] = f2fma(f0, x0.x, fA[e]);
                    fB[e] = f2fma(f1, x0.y, fB[e]);
                    fA[e] = f2fma(f2, x1.x, fA[e]);
                    fB[e] = f2fma(f3, x1.y, fB[e]);
                    gA[e] = f2fma(g0, x0.x, gA[e]);
                    gB[e] = f2fma(g1, x0.y, gB[e]);
                    gA[e] = f2fma(g2, x1.x, gA[e]);
                    gB[e] = f2fma(g3, x1.y, gB[e]);
                }
            }
#pragma unroll
            for (int e = 0; e < 2; e++) {
                u64 tf = f2add(fA[e], fB[e]);
                u64 tg = f2add(gA[e], gB[e]);
                float lo, hi;
                unpk2(tf, lo, hi);
                sm.h1f[p0 + e][idx] = make_float2(softplus1(lo), softplus1(hi));
                unpk2(tg, lo, hi);
                sm.h1g[p0 + e][idx] = make_float2(softplus1(lo), softplus1(hi));
            }
        }
        tbar(team);

        // ===== ph2: f layer2 + g layer2 for team's 2 pairs =====
        {
            u64 z0 = dup2f(0.f);
            u64 fi = dup2f(bf2), gi = dup2f(bg2);
            u64 fA[2] = { fi, fi }, fB[2] = { z0, z0 };
            u64 gA[2] = { gi, gi }, gB[2] = { z0, z0 };
#pragma unroll 4
            for (int c = 0; c < Hn / 4; c++) {
                float4 wf = *(const float4*)&sm.fW2t[idx][4 * c];
                float4 wgv = *(const float4*)&sm.gW2t[idx][4 * c];
                u64 f0 = dup2f(wf.x), f1 = dup2f(wf.y), f2 = dup2f(wf.z), f3 = dup2f(wf.w);
                u64 g0 = dup2f(wgv.x), g1 = dup2f(wgv.y), g2 = dup2f(wgv.z), g3 = dup2f(wgv.w);
#pragma unroll
                for (int e = 0; e < 2; e++) {
                    ulonglong2 xf0 = *(const ulonglong2*)&sm.h1f[p0 + e][4 * c];
                    ulonglong2 xf1 = *(const ulonglong2*)&sm.h1f[p0 + e][4 * c + 2];
                    fA[e] = f2fma(f0, xf0.x, fA[e]);
                    fB[e] = f2fma(f1, xf0.y, fB[e]);
                    fA[e] = f2fma(f2, xf1.x, fA[e]);
                    fB[e] = f2fma(f3, xf1.y, fB[e]);
                    ulonglong2 xg0 = *(const ulonglong2*)&sm.h1g[p0 + e][4 * c];
                    ulonglong2 xg1 = *(const ulonglong2*)&sm.h1g[p0 + e][4 * c + 2];
                    gA[e] = f2fma(g0, xg0.x, gA[e]);
                    gB[e] = f2fma(g1, xg0.y, gB[e]);
                    gA[e] = f2fma(g2, xg1.x, gA[e]);
                    gB[e] = f2fma(g3, xg1.y, gB[e]);
                }
            }
#pragma unroll
            for (int e = 0; e < 2; e++) {
                u64 tf = f2add(fA[e], fB[e]);
                u64 tg = f2add(gA[e], gB[e]);
                float lo, hi;
                unpk2(tf, lo, hi);
                sm.h2f[p0 + e][idx] = make_float2(softplus1(lo), softplus1(hi));
                unpk2(tg, lo, hi);
                sm.h2g[p0 + e][idx] = make_float2(softplus1(lo), softplus1(hi));
            }
        }
        tbar(team);

        // ===== ph3: f3 + g3 (team-local; gW3 read once per team) =====
        u64 paR[2];   // einsum results for pairs p0, p0+1 at l = lz (valid post-shfl)
        {
            const u64 one2 = dup2f(1.f);
            // f3: pair qf, output lf (h2f reads are warp-broadcasts)
            u64 a0 = dup2f(bf3v), a1 = dup2f(0.f);
            const float* fp = fW3 + lf;
            // g3: outputs 4idx..4idx+3 for team's 2 pairs
            u64 acc[2][4];
#pragma unroll
            for (int i = 0; i < 4; i++) {
                acc[0][i] = dup2f(bg3a[i]);
                acc[1][i] = acc[0][i];
            }
            const float4* g4 = reinterpret_cast<const float4*>(gW3) + idx;
#pragma unroll 4
            for (int c = 0; c < Hn / 2; c++) {
                // f3: k = 2c, 2c+1
                u64 w0 = dup2f(__ldg(fp + (2 * c) * Ln));
                u64 w1 = dup2f(__ldg(fp + (2 * c + 1) * Ln));
                a0 = f2fma(w0, *(const u64*)&sm.h2f[qf][2 * c], a0);
                a1 = f2fma(w1, *(const u64*)&sm.h2f[qf][2 * c + 1], a1);
                // g3: k-rows 2c, 2c+1 (float4, coalesced per warp)
                float4 wa = __ldg(g4 + (size_t)(2 * c) * (Ln * Nn / 4));
                float4 wb = __ldg(g4 + (size_t)(2 * c + 1) * (Ln * Nn / 4));
                u64 wa0 = dup2f(wa.x), wa1 = dup2f(wa.y), wa2 = dup2f(wa.z), wa3 = dup2f(wa.w);
                u64 wb0 = dup2f(wb.x), wb1 = dup2f(wb.y), wb2 = dup2f(wb.z), wb3 = dup2f(wb.w);
#pragma unroll
                for (int e = 0; e < 2; e++) {
                    ulonglong2 h = *(const ulonglong2*)&sm.h2g[p0 + e][2 * c];
                    acc[e][0] = f2fma(wa0, h.x, acc[e][0]);
                    acc[e][1] = f2fma(wa1, h.x, acc[e][1]);
                    acc[e][2] = f2fma(wa2, h.x, acc[e][2]);
                    acc[e][3] = f2fma(wa3, h.x, acc[e][3]);
                    acc[e][0] = f2fma(wb0, h.y, acc[e][0]);
                    acc[e][1] = f2fma(wb1, h.y, acc[e][1]);
                    acc[e][2] = f2fma(wb2, h.y, acc[e][2]);
                    acc[e][3] = f2fma(wb3, h.y, acc[e][3]);
                }
            }
            // f3 output -> foT (team-local region; pairs p0..p0+1)
            {
                u64 t = f2add(a0, a1);
                float lo, hi; unpk2(t, lo, hi);
                sm.foT[qf][lf] = make_float2(tanh1(lo), tanh1(hi));
            }
            // einsum partials: outputs at l = idx>>1, n's = (idx&1)*4 .. +3;
            // shfl_xor(1) combines the two n-halves -> both lanes hold full sum
            const int nb = (idx & 1) * 4;
#pragma unroll
            for (int e = 0; e < 2; e++) {
                u64 pa = dup2f(0.f);
#pragma unroll
                for (int i = 0; i < 4; i++)
                    pa = f2fma(tanh2(acc[e][i]), *(const u64*)&sm.dws[p0 + e][nb + i], pa);
                pa = f2fma(one2, __shfl_xor_sync(0xffffffffu, pa, 1), pa);
                paR[e] = pa;
            }
        }
        tbar(team);   // foT visible

        // ===== ph4: z update — thread = (pair p0+ez, l = lz) =====
        {
            const u64 one2 = dup2f(1.f);
            const int p = p0 + ez;
            u64 z = *(const u64*)&sm.z2[p][lz];
            z = f2fma(*(const u64*)&sm.foT[p][lz], dup2f(dt), z);
            z = f2fma(one2, paR[ez], z);
            *(u64*)&sm.z2[p][lz] = z;
            zbuf[((size_t)(s + 1) * NCTA + blockIdx.x) * (PAIRS * Ln)
                 + p * Ln + lz] = z;
        }
        tbar(team);   // z2 stable before next ph1
    }
}

// ---------------- readout kernel: x = relu(z@rW1+b1)@rW2+b2 ------------------
#define RO_TS 32   /* time steps per block */
struct __align__(16) RoSmem {
    float rw1t[Hn][68];     // rW1 transposed [j][l]
    float w2t[DOn][130];    // rW2 transposed [d][k], pad 130
    float2 zt[PAIRS][Ln];   // current z tile (2 KB)
    float h1T[RROWS][132];  // stage-1 output, scalar per row, pad 132
};

__global__ void __launch_bounds__(256, 4)
readout_kernel(const float* __restrict__ rW1, const float* __restrict__ rb1,
               const float* __restrict__ rW2, const float* __restrict__ rb2,
               float* __restrict__ out)
{
    extern __shared__ __align__(16) char smraw[];
    RoSmem& sm = *reinterpret_cast<RoSmem*>(smraw);
    const int tid = threadIdx.x;
    const int cta = blockIdx.x & (NCTA - 1);
    const int slice = blockIdx.x >> 7;
    const int rowbase = cta * RROWS;

    // stage rW1 transposed: [j][l], coalesced LDG over j
    {
        const int jj = tid & 127, half = tid >> 7;
#pragma unroll 4
        for (int l = half * 32; l < half * 32 + 32; l++)
            sm.rw1t[jj][l] = rW1[l * Hn + jj];
    }
    // stage rW2 transposed: [d][k]
    for (int i = tid; i < Hn * DOn; i += 256) {
        int d = i & 15, k = i >> 4;
        sm.w2t[d][k] = rW2[i];
    }
    const float rb1v = __ldg(rb1 + (tid & 127));
    const int jr = tid & 127, p0 = (tid >> 7) * 2;             // stage-1 mapping
    const int row2 = tid >> 5, kh5 = (tid >> 4) & 1, d5 = tid & 15;  // stage-2
    const float rb2v = __ldg(rb2 + d5);
    __syncthreads();

    for (int it = 0; it < RO_TS; it++) {
        const int t = slice * RO_TS + it;
        // load z tile
        ((u64*)&sm.zt[0][0])[tid] =
            zbuf[((size_t)t * NCTA + cta) * (PAIRS * Ln) + tid];
        __syncthreads();
        // stage 1: h = relu(z @ rW1 + b1); thread = (jr, 2 pairs); write h1T
        {
            u64 aA[2], aB[2];
            u64 bi = dup2f(rb1v), z0 = dup2f(0.f);
            aA[0] = bi; aA[1] = bi; aB[0] = z0; aB[1] = z0;
#pragma unroll 4
            for (int c = 0; c < Ln / 4; c++) {
                float4 w = *(const float4*)&sm.rw1t[jr][4 * c];
                u64 w0 = dup2f(w.x), w1 = dup2f(w.y), w2 = dup2f(w.z), w3 = dup2f(w.w);
#pragma unroll
                for (int e = 0; e < 2; e++) {
                    ulonglong2 x0 = *(const ulonglong2*)&sm.zt[p0 + e][4 * c];
                    ulonglong2 x1 = *(const ulonglong2*)&sm.zt[p0 + e][4 * c + 2];
                    aA[e] = f2fma(w0, x0.x, aA[e]);
                    aB[e] = f2fma(w1, x0.y, aB[e]);
                    aA[e] = f2fma(w2, x1.x, aA[e]);
                    aB[e] = f2fma(w3, x1.y, aB[e]);
                }
            }
#pragma unroll
            for (int e = 0; e < 2; e++) {
                u64 tv = f2add(aA[e], aB[e]);
                float lo, hi; unpk2(tv, lo, hi);
                sm.h1T[2 * (p0 + e)][jr]     = fmaxf(lo, 0.f);
                sm.h1T[2 * (p0 + e) + 1][jr] = fmaxf(hi, 0.f);
            }
        }
        __syncthreads();
        // stage 2: x = h @ rW2 + b2; thread = (row2, kh5, d5), f32x2 over k-pairs
        {
            u64 acc = dup2f(0.f);
            const float* hT = &sm.h1T[row2][kh5 * 64];
            const float* wT = &sm.w2t[d5][kh5 * 64];
#pragma unroll 8
            for (int kk = 0; kk < 64; kk += 2)
                acc = f2fma(*(const u64*)&hT[kk], *(const u64*)&wT[kk], acc);
            float lo, hi; unpk2(acc, lo, hi);
            float a = lo + hi;
            a += __shfl_xor_sync(0xffffffffu, a, 16);
            if (kh5 == 0) {
                a += rb2v;
                size_t row = (size_t)rowbase + row2;
                out[(row * Tn + t) * DOn + d5] = a;
                if ((t & 7) == 0)
                    out[XFULL + (row * (Tn / 8) + (t >> 3)) * DOn + d5] = a;
            }
        }
        __syncthreads();
    }
}

extern "C" void kernel_launch(void* const* d_in, const int* in_sizes, int n_in,
                              void* d_out, int out_size) {
    (void)in_sizes; (void)n_in; (void)out_size;
    cudaFuncSetAttribute(sde_scan_kernel, cudaFuncAttributeMaxDynamicSharedMemorySize,
                         (int)sizeof(Smem));
    cudaFuncSetAttribute(readout_kernel, cudaFuncAttributeMaxDynamicSharedMemorySize,
                         (int)sizeof(RoSmem));
    sde_scan_kernel<<<NCTA, NTHR, sizeof(Smem)>>>(
        (const float*)d_in[0],  (const float*)d_in[1],  (const float*)d_in[2],
        (const float*)d_in[3],  (const float*)d_in[4],  (const float*)d_in[5],
        (const float*)d_in[6],  (const float*)d_in[7],  (const float*)d_in[8],
        (const float*)d_in[9],  (const float*)d_in[10], (const float*)d_in[11],
        (const float*)d_in[12], (const float*)d_in[13], (const float*)d_in[14],
        (const float*)d_in[15], (const float*)d_in[16]);
    readout_kernel<<<NCTA * (Tn / RO_TS), 256, sizeof(RoSmem)>>>(
        (const float*)d_in[17], (const float*)d_in[18],
        (const float*)d_in[19], (const float*)d_in[20],
        (float*)d_out);
}

// round 16
// speedup vs baseline: 1.0987x; 1.0817x over previous
#include <cuda_runtime.h>
#include <cstdint>

typedef unsigned long long u64;

#define Bn 1024
#define Tn 512
#define Ln 64
#define Nn 8
#define Hn 128
#define DIn 32
#define DOn 16
#define RROWS 8
#define PAIRS 4
#define NCTA (Bn / RROWS)   /* 128 */
#define NTHR 256
#define XFULL ((size_t)Bn * Tn * DOn)

// z-path scratch: [t][cta][pair][l] as packed float2 (u64). 128 MB.
__device__ u64 zbuf[(size_t)Tn * NCTA * PAIRS * Ln];

// ---------------- scan-kernel shared memory (~223 KB) ------------------------
struct __align__(16) Smem {
    float fW1t[Hn][68];    // f_W1 z-part transposed [j][k]; 68 == 4 (mod 32)
    float fW2t[Hn][132];   // f_W2 transposed; 132 == 4 (mod 32)
    float gW1t[Hn][68];
    float gW2t[Hn][132];
    float2 z2[PAIRS][Ln];  // state, row-pairs packed: .x = row 2p, .y = row 2p+1
    float2 h1f[PAIRS][Hn]; // aliased as fo[4][64] during ph3/ph4
    float2 h2f[PAIRS][Hn];
    float2 h1g[PAIRS][Hn]; // aliased as geo[4][64] during ph3/ph4
    float2 h2g[PAIRS][Hn];
    float2 dws[PAIRS][Nn];
};

// ---------------- f32x2 packed helpers ---------------------------------------
__device__ __forceinline__ u64 dup2f(float v) {
    u64 r; asm("mov.b64 %0,{%1,%1};" : "=l"(r) : "f"(v)); return r;
}
__device__ __forceinline__ u64 pk2(float lo, float hi) {
    u64 r; asm("mov.b64 %0,{%1,%2};" : "=l"(r) : "f"(lo), "f"(hi)); return r;
}
__device__ __forceinline__ void unpk2(u64 v, float& lo, float& hi) {
    asm("mov.b64 {%0,%1},%2;" : "=f"(lo), "=f"(hi) : "l"(v));
}
__device__ __forceinline__ u64 f2fma(u64 a, u64 b, u64 c) {
    u64 d; asm("fma.rn.f32x2 %0,%1,%2,%3;" : "=l"(d) : "l"(a), "l"(b), "l"(c)); return d;
}
__device__ __forceinline__ u64 f2add(u64 a, u64 b) {
    u64 d; asm("add.rn.f32x2 %0,%1,%2;" : "=l"(d) : "l"(a), "l"(b)); return d;
}

// softplus(x) = max(x,0) + log1p(exp(-|x|))
__device__ __forceinline__ float softplus1(float x) {
    float e = __expf(-fabsf(x));
    return fmaxf(x, 0.f) + 0.69314718055994531f * __log2f(1.f + e);
}
// tanh(x) = 1 - 2/(exp(2x)+1)
__device__ __forceinline__ float tanh1(float x) {
    float e = __expf(2.f * x);
    return 1.f - __fdividef(2.f, e + 1.f);
}

// ---------------- main persistent scan kernel (R11, unchanged) ---------------
__global__ void __launch_bounds__(NTHR, 1)
sde_scan_kernel(const float* __restrict__ init_noise, const float* __restrict__ dw_noise,
                const float* __restrict__ ts,   const float* __restrict__ embW,
                const float* __restrict__ embb, const float* __restrict__ fW1,
                const float* __restrict__ fb1,  const float* __restrict__ fW2,
                const float* __restrict__ fb2,  const float* __restrict__ fW3,
                const float* __restrict__ fb3,  const float* __restrict__ gW1,
                const float* __restrict__ gb1,  const float* __restrict__ gW2,
                const float* __restrict__ gb2,  const float* __restrict__ gW3,
                const float* __restrict__ gb3)
{
    extern __shared__ __align__(16) char smraw[];
    Smem& sm = *reinterpret_cast<Smem*>(smraw);
    const int tid = threadIdx.x;
    const int wg = tid & 127;            // layer neuron
    const int team = tid >> 7;           // 0,1
    const int p0 = 2 * team;             // team's pairs (ph1/ph2)
    const int rowbase = blockIdx.x * RROWS;

    // aliases over buffers that are dead during ph3/ph4
    float2 (*fo)[Ln]  = reinterpret_cast<float2(*)[Ln]>(&sm.h1f[0][0]);
    float2 (*geo)[Ln] = reinterpret_cast<float2(*)[Ln]>(&sm.h1g[0][0]);

    // ---- stage SMEM-resident weights (team-split) ----
    {
        const int j = wg;
        if (team == 0) {
#pragma unroll 4
            for (int k = 0; k < Ln; k++) sm.fW1t[j][k] = fW1[(k + 1) * Hn + j];
#pragma unroll 4
            for (int k = 0; k < Hn; k++) sm.fW2t[j][k] = fW2[k * Hn + j];
        } else {
#pragma unroll 4
            for (int k = 0; k < Ln; k++) sm.gW1t[j][k] = gW1[(k + 1) * Hn + j];
#pragma unroll 4
            for (int k = 0; k < Hn; k++) sm.gW2t[j][k] = gW2[k * Hn + j];
        }
    }

    // ---- per-thread register params ----
    const float w10f = __ldg(fW1 + wg), w10g = __ldg(gW1 + wg);
    const float bf1 = __ldg(fb1 + wg), bf2 = __ldg(fb2 + wg);
    const float bg1 = __ldg(gb1 + wg), bg2 = __ldg(gb2 + wg);
    const int l3 = tid & 63, q3 = tid >> 6;            // f3 mapping (4 pairs x 64 l)
    const float bf3v = __ldg(fb3 + l3);
    const float2 bg3v = *(const float2*)(gb3 + 2 * tid);  // outputs 2tid, 2tid+1

    // ---- z0 = init_noise @ emb_W + emb_b; store to zbuf[t=0] ----
    {
        int l = tid & 63, p = tid >> 6;
        float ax = __ldg(embb + l), ay = ax;
#pragma unroll 4
        for (int i = 0; i < DIn; i++) {
            float w = embW[i * Ln + l];
            ax = fmaf(init_noise[(rowbase + 2 * p) * DIn + i], w, ax);
            ay = fmaf(init_noise[(rowbase + 2 * p + 1) * DIn + i], w, ay);
        }
        sm.z2[p][l] = make_float2(ax, ay);
        zbuf[(size_t)blockIdx.x * (PAIRS * Ln) + tid] = *(const u64*)&sm.z2[p][l];
    }
    __syncthreads();

    // ---- 511 Euler-Maruyama steps, 4 barriers each --------------------------
    for (int s = 0; s < Tn - 1; s++) {
        const float tcur = __ldg(ts + s);
        const float dt = __ldg(ts + s + 1) - tcur;
        const float sq = sqrtf(dt);
        if (tid < 32) {   // Brownian increments (consumed in ph3, >=2 bars later)
            int p = tid >> 3, n = tid & 7;
            const float* dwp = dw_noise + ((size_t)s * Bn + rowbase + 2 * p) * Nn + n;
            sm.dws[p][n] = make_float2(dwp[0] * sq, dwp[Nn] * sq);
        }

        // ===== ph1: f layer1 + g layer1 (shared z2 act loads, 8 chains) =====
        {
            u64 z0 = dup2f(0.f);
            u64 fi = dup2f(fmaf(w10f, tcur, bf1));
            u64 gi = dup2f(fmaf(w10g, tcur, bg1));
            u64 fA[2] = { fi, fi }, fB[2] = { z0, z0 };
            u64 gA[2] = { gi, gi }, gB[2] = { z0, z0 };
#pragma unroll 4
            for (int c = 0; c < Ln / 4; c++) {
                float4 wf = *(const float4*)&sm.fW1t[wg][4 * c];
                float4 wgv = *(const float4*)&sm.gW1t[wg][4 * c];
                u64 f0 = dup2f(wf.x), f1 = dup2f(wf.y), f2 = dup2f(wf.z), f3 = dup2f(wf.w);
                u64 g0 = dup2f(wgv.x), g1 = dup2f(wgv.y), g2 = dup2f(wgv.z), g3 = dup2f(wgv.w);
#pragma unroll
                for (int e = 0; e < 2; e++) {
                    ulonglong2 x0 = *(const ulonglong2*)&sm.z2[p0 + e][4 * c];
                    ulonglong2 x1 = *(const ulonglong2*)&sm.z2[p0 + e][4 * c + 2];
                    fA[e] = f2fma(f0, x0.x, fA[e]);
                    fB[e] = f2fma(f1, x0.y, fB[e]);
                    fA[e] = f2fma(f2, x1.x, fA[e]);
                    fB[e] = f2fma(f3, x1.y, fB[e]);
                    gA[e] = f2fma(g0, x0.x, gA[e]);
                    gB[e] = f2fma(g1, x0.y, gB[e]);
                    gA[e] = f2fma(g2, x1.x, gA[e]);
                    gB[e] = f2fma(g3, x1.y, gB[e]);
                }
            }
#pragma unroll
            for (int e = 0; e < 2; e++) {
                u64 tf = f2add(fA[e], fB[e]);
                u64 tg = f2add(gA[e], gB[e]);
                float lo, hi;
                unpk2(tf, lo, hi);
                sm.h1f[p0 + e][wg] = make_float2(softplus1(lo), softplus1(hi));
                unpk2(tg, lo, hi);
                sm.h1g[p0 + e][wg] = make_float2(softplus1(lo), softplus1(hi));
            }
        }
        __syncthreads();

        // ===== ph2: f layer2 + g layer2 =====
        {
            u64 z0 = dup2f(0.f);
            u64 fi = dup2f(bf2), gi = dup2f(bg2);
            u64 fA[2] = { fi, fi }, fB[2] = { z0, z0 };
            u64 gA[2] = { gi, gi }, gB[2] = { z0, z0 };
#pragma unroll 4
            for (int c = 0; c < Hn / 4; c++) {
                float4 wf = *(const float4*)&sm.fW2t[wg][4 * c];
                float4 wgv = *(const float4*)&sm.gW2t[wg][4 * c];
                u64 f0 = dup2f(wf.x), f1 = dup2f(wf.y), f2 = dup2f(wf.z), f3 = dup2f(wf.w);
                u64 g0 = dup2f(wgv.x), g1 = dup2f(wgv.y), g2 = dup2f(wgv.z), g3 = dup2f(wgv.w);
#pragma unroll
                for (int e = 0; e < 2; e++) {
                    ulonglong2 xf0 = *(const ulonglong2*)&sm.h1f[p0 + e][4 * c];
                    ulonglong2 xf1 = *(const ulonglong2*)&sm.h1f[p0 + e][4 * c + 2];
                    fA[e] = f2fma(f0, xf0.x, fA[e]);
                    fB[e] = f2fma(f1, xf0.y, fB[e]);
                    fA[e] = f2fma(f2, xf1.x, fA[e]);
                    fB[e] = f2fma(f3, xf1.y, fB[e]);
                    ulonglong2 xg0 = *(const ulonglong2*)&sm.h1g[p0 + e][4 * c];
                    ulonglong2 xg1 = *(const ulonglong2*)&sm.h1g[p0 + e][4 * c + 2];
                    gA[e] = f2fma(g0, xg0.x, gA[e]);
                    gB[e] = f2fma(g1, xg0.y, gB[e]);
                    gA[e] = f2fma(g2, xg1.x, gA[e]);
                    gB[e] = f2fma(g3, xg1.y, gB[e]);
                }
            }
#pragma unroll
            for (int e = 0; e < 2; e++) {
                u64 tf = f2add(fA[e], fB[e]);
                u64 tg = f2add(gA[e], gB[e]);
                float lo, hi;
                unpk2(tf, lo, hi);
                sm.h2f[p0 + e][wg] = make_float2(softplus1(lo), softplus1(hi));
                unpk2(tg, lo, hi);
                sm.h2g[p0 + e][wg] = make_float2(softplus1(lo), softplus1(hi));
            }
        }
        __syncthreads();

        // ===== ph3: f3 (thread=(l3,q3)) fused with g3 (R8 schedule) =====
        {
            const u64 one2 = dup2f(1.f);
            u64 a0 = dup2f(bf3v), a1 = dup2f(0.f);
            const float* fp = fW3 + l3;
            u64 acc[PAIRS][2];
#pragma unroll
            for (int p = 0; p < PAIRS; p++) {
                acc[p][0] = dup2f(bg3v.x);
                acc[p][1] = dup2f(bg3v.y);
            }
            const float2* g2 = reinterpret_cast<const float2*>(gW3) + tid;
#pragma unroll 4
            for (int c = 0; c < Hn / 2; c++) {
                // f3: k = 2c, 2c+1
                u64 w0 = dup2f(__ldg(fp + (2 * c) * Ln));
                u64 w1 = dup2f(__ldg(fp + (2 * c + 1) * Ln));
                a0 = f2fma(w0, *(const u64*)&sm.h2f[q3][2 * c], a0);
                a1 = f2fma(w1, *(const u64*)&sm.h2f[q3][2 * c + 1], a1);
                // g3: k-rows 2c, 2c+1 (LDG.64, fully coalesced over warp)
                float2 va = __ldg(g2 + (size_t)(2 * c) * (Ln * Nn / 2));
                float2 vb = __ldg(g2 + (size_t)(2 * c + 1) * (Ln * Nn / 2));
                u64 wa0 = dup2f(va.x), wa1 = dup2f(va.y);
                u64 wb0 = dup2f(vb.x), wb1 = dup2f(vb.y);
#pragma unroll
                for (int p = 0; p < PAIRS; p++) {
                    ulonglong2 h = *(const ulonglong2*)&sm.h2g[p][2 * c];
                    acc[p][0] = f2fma(wa0, h.x, acc[p][0]);
                    acc[p][1] = f2fma(wa1, h.x, acc[p][1]);
                    acc[p][0] = f2fma(wb0, h.y, acc[p][0]);
                    acc[p][1] = f2fma(wb1, h.y, acc[p][1]);
                }
            }
            // f3 output -> fo (h1f alias; h1f dead this phase)
            {
                u64 t = f2add(a0, a1);
                float lo, hi; unpk2(t, lo, hi);
                fo[q3][l3] = make_float2(tanh1(lo), tanh1(hi));
            }
            // einsum: l = tid>>2, n's = (tid&3)*2, +1; reduce 4 lanes via shfl
            const int l = tid >> 2, nb = (tid & 3) * 2;
#pragma unroll
            for (int p = 0; p < PAIRS; p++) {
                float x0, x1, y0, y1;
                unpk2(acc[p][0], x0, x1);
                unpk2(acc[p][1], y0, y1);
                u64 t0 = pk2(tanh1(x0), tanh1(x1));
                u64 t1 = pk2(tanh1(y0), tanh1(y1));
                u64 pa = f2fma(t0, *(const u64*)&sm.dws[p][nb], dup2f(0.f));
                pa = f2fma(t1, *(const u64*)&sm.dws[p][nb + 1], pa);
                pa = f2fma(one2, __shfl_xor_sync(0xffffffffu, pa, 1), pa);
                pa = f2fma(one2, __shfl_xor_sync(0xffffffffu, pa, 2), pa);
                if ((tid & 3) == 0) *(u64*)&geo[p][l] = pa;
            }
        }
        __syncthreads();

        // ===== ph4: z update (thread = (p,l)) + stream z to global =====
        {
            int l = tid & 63, p = tid >> 6;
            const u64 one2 = dup2f(1.f);
            u64 dt2 = dup2f(dt);
            u64 z = *(const u64*)&sm.z2[p][l];
            z = f2fma(*(const u64*)&fo[p][l], dt2, z);
            z = f2fma(one2, *(const u64*)&geo[p][l], z);
            *(u64*)&sm.z2[p][l] = z;
            zbuf[((size_t)(s + 1) * NCTA + blockIdx.x) * (PAIRS * Ln) + tid] = z;
        }
        __syncthreads();
    }
}

// ---------------- readout kernel: x = relu(z@rW1+b1)@rW2+b2 ------------------
// Two time steps per iteration: weights loaded once serve 2x the FMA work;
// barrier count halves.
#define RO_TS 32   /* time steps per block */
struct __align__(16) RoSmem {
    float rw1t[Hn][68];       // rW1 transposed [j][l]
    float w2t[DOn][130];      // rW2 transposed [d][k], pad 130
    float2 zt[2][PAIRS][Ln];  // two z tiles (4 KB)
    float h1T[2][RROWS][132]; // stage-1 outputs for both t (8.25 KB)
};

__global__ void __launch_bounds__(256, 4)
readout_kernel(const float* __restrict__ rW1, const float* __restrict__ rb1,
               const float* __restrict__ rW2, const float* __restrict__ rb2,
               float* __restrict__ out)
{
    extern __shared__ __align__(16) char smraw[];
    RoSmem& sm = *reinterpret_cast<RoSmem*>(smraw);
    const int tid = threadIdx.x;
    const int cta = blockIdx.x & (NCTA - 1);
    const int slice = blockIdx.x >> 7;
    const int rowbase = cta * RROWS;

    // stage rW1 transposed: [j][l], coalesced LDG over j
    {
        const int jj = tid & 127, half = tid >> 7;
#pragma unroll 4
        for (int l = half * 32; l < half * 32 + 32; l++)
            sm.rw1t[jj][l] = rW1[l * Hn + jj];
    }
    // stage rW2 transposed: [d][k]
    for (int i = tid; i < Hn * DOn; i += 256) {
        int d = i & 15, k = i >> 4;
        sm.w2t[d][k] = rW2[i];
    }
    const float rb1v = __ldg(rb1 + (tid & 127));
    const int jr = tid & 127, p0 = (tid >> 7) * 2;             // stage-1 mapping
    const int row2 = tid >> 5, kh5 = (tid >> 4) & 1, d5 = tid & 15;  // stage-2
    const float rb2v = __ldg(rb2 + d5);
    __syncthreads();

    for (int it = 0; it < RO_TS / 2; it++) {
        const int t0 = slice * RO_TS + 2 * it;
        // load both z tiles
        {
            size_t base = ((size_t)t0 * NCTA + cta) * (PAIRS * Ln);
            ((u64*)&sm.zt[0][0][0])[tid] = zbuf[base + tid];
            ((u64*)&sm.zt[1][0][0])[tid] =
                zbuf[base + (size_t)NCTA * (PAIRS * Ln) + tid];
        }
        __syncthreads();
        // stage 1: h = relu(z @ rW1 + b1) for BOTH t; thread = (jr, 2 pairs)
        {
            u64 aA[2][2], aB[2][2];
            u64 bi = dup2f(rb1v), z0 = dup2f(0.f);
#pragma unroll
            for (int tt = 0; tt < 2; tt++) {
                aA[tt][0] = bi; aA[tt][1] = bi;
                aB[tt][0] = z0; aB[tt][1] = z0;
            }
#pragma unroll 4
            for (int c = 0; c < Ln / 4; c++) {
                float4 w = *(const float4*)&sm.rw1t[jr][4 * c];
                u64 w0 = dup2f(w.x), w1 = dup2f(w.y), w2 = dup2f(w.z), w3 = dup2f(w.w);
#pragma unroll
                for (int tt = 0; tt < 2; tt++) {
#pragma unroll
                    for (int e = 0; e < 2; e++) {
                        ulonglong2 x0 = *(const ulonglong2*)&sm.zt[tt][p0 + e][4 * c];
                        ulonglong2 x1 = *(const ulonglong2*)&sm.zt[tt][p0 + e][4 * c + 2];
                        aA[tt][e] = f2fma(w0, x0.x, aA[tt][e]);
                        aB[tt][e] = f2fma(w1, x0.y, aB[tt][e]);
                        aA[tt][e] = f2fma(w2, x1.x, aA[tt][e]);
                        aB[tt][e] = f2fma(w3, x1.y, aB[tt][e]);
                    }
                }
            }
#pragma unroll
            for (int tt = 0; tt < 2; tt++)
#pragma unroll
                for (int e = 0; e < 2; e++) {
                    u64 tv = f2add(aA[tt][e], aB[tt][e]);
                    float lo, hi; unpk2(tv, lo, hi);
                    sm.h1T[tt][2 * (p0 + e)][jr]     = fmaxf(lo, 0.f);
                    sm.h1T[tt][2 * (p0 + e) + 1][jr] = fmaxf(hi, 0.f);
                }
        }
        __syncthreads();
        // stage 2: x = h @ rW2 + b2 for BOTH t; thread = (row2, kh5, d5)
        {
            u64 acc0 = dup2f(0.f), acc1 = dup2f(0.f);
            const float* hT0 = &sm.h1T[0][row2][kh5 * 64];
            const float* hT1 = &sm.h1T[1][row2][kh5 * 64];
            const float* wT = &sm.w2t[d5][kh5 * 64];
#pragma unroll 8
            for (int kk = 0; kk < 64; kk += 2) {
                u64 wv = *(const u64*)&wT[kk];
                acc0 = f2fma(*(const u64*)&hT0[kk], wv, acc0);
                acc1 = f2fma(*(const u64*)&hT1[kk], wv, acc1);
            }
            float a0, a1;
            { float lo, hi; unpk2(acc0, lo, hi); a0 = lo + hi; }
            { float lo, hi; unpk2(acc1, lo, hi); a1 = lo + hi; }
            a0 += __shfl_xor_sync(0xffffffffu, a0, 16);
            a1 += __shfl_xor_sync(0xffffffffu, a1, 16);
            if (kh5 == 0) {
                a0 += rb2v; a1 += rb2v;
                size_t row = (size_t)rowbase + row2;
                out[(row * Tn + t0) * DOn + d5] = a0;
                out[(row * Tn + t0 + 1) * DOn + d5] = a1;
                if ((t0 & 7) == 0)
                    out[XFULL + (row * (Tn / 8) + (t0 >> 3)) * DOn + d5] = a0;
            }
        }
        __syncthreads();
    }
}

extern "C" void kernel_launch(void* const* d_in, const int* in_sizes, int n_in,
                              void* d_out, int out_size) {
    (void)in_sizes; (void)n_in; (void)out_size;
    cudaFuncSetAttribute(sde_scan_kernel, cudaFuncAttributeMaxDynamicSharedMemorySize,
                         (int)sizeof(Smem));
    cudaFuncSetAttribute(readout_kernel, cudaFuncAttributeMaxDynamicSharedMemorySize,
                         (int)sizeof(RoSmem));
    sde_scan_kernel<<<NCTA, NTHR, sizeof(Smem)>>>(
        (const float*)d_in[0],  (const float*)d_in[1],  (const float*)d_in[2],
        (const float*)d_in[3],  (const float*)d_in[4],  (const float*)d_in[5],
        (const float*)d_in[6],  (const float*)d_in[7],  (const float*)d_in[8],
        (const float*)d_in[9],  (const float*)d_in[10], (const float*)d_in[11],
        (const float*)d_in[12], (const float*)d_in[13], (const float*)d_in[14],
        (const float*)d_in[15], (const float*)d_in[16]);
    readout_kernel<<<NCTA * (Tn / RO_TS), 256, sizeof(RoSmem)>>>(
        (const float*)d_in[17], (const float*)d_in[18],
        (const float*)d_in[19], (const float*)d_in[20],
        (float*)d_out);
}

// round 17
// speedup vs baseline: 1.1075x; 1.0081x over previous
#include <cuda_runtime.h>
#include <cstdint>

typedef unsigned long long u64;

#define Bn 1024
#define Tn 512
#define Ln 64
#define Nn 8
#define Hn 128
#define DIn 32
#define DOn 16
#define RROWS 8
#define PAIRS 4
#define NCTA (Bn / RROWS)   /* 128 */
#define NTHR 256
#define XFULL ((size_t)Bn * Tn * DOn)

// z-path scratch: [t][cta][pair][l] as packed float2 (u64). 128 MB.
__device__ u64 zbuf[(size_t)Tn * NCTA * PAIRS * Ln];

// ---------------- scan-kernel shared memory (~223 KB) ------------------------
struct __align__(16) Smem {
    float fW1t[Hn][68];    // f_W1 z-part transposed [j][k]; 68 == 4 (mod 32)
    float fW2t[Hn][132];   // f_W2 transposed; 132 == 4 (mod 32)
    float gW1t[Hn][68];
    float gW2t[Hn][132];
    float2 z2[PAIRS][Ln];  // state, row-pairs packed: .x = row 2p, .y = row 2p+1
    float2 h1f[PAIRS][Hn]; // aliased as fo[4][64] during ph3/ph4
    float2 h2f[PAIRS][Hn];
    float2 h1g[PAIRS][Hn]; // aliased as geo[4][64] during ph3/ph4
    float2 h2g[PAIRS][Hn];
    float2 dws[PAIRS][Nn];
};

// ---------------- f32x2 packed helpers ---------------------------------------
__device__ __forceinline__ u64 dup2f(float v) {
    u64 r; asm("mov.b64 %0,{%1,%1};" : "=l"(r) : "f"(v)); return r;
}
__device__ __forceinline__ u64 pk2(float lo, float hi) {
    u64 r; asm("mov.b64 %0,{%1,%2};" : "=l"(r) : "f"(lo), "f"(hi)); return r;
}
__device__ __forceinline__ void unpk2(u64 v, float& lo, float& hi) {
    asm("mov.b64 {%0,%1},%2;" : "=f"(lo), "=f"(hi) : "l"(v));
}
__device__ __forceinline__ u64 f2fma(u64 a, u64 b, u64 c) {
    u64 d; asm("fma.rn.f32x2 %0,%1,%2,%3;" : "=l"(d) : "l"(a), "l"(b), "l"(c)); return d;
}
__device__ __forceinline__ u64 f2add(u64 a, u64 b) {
    u64 d; asm("add.rn.f32x2 %0,%1,%2;" : "=l"(d) : "l"(a), "l"(b)); return d;
}

// softplus(x) = max(x,0) + log1p(exp(-|x|))
__device__ __forceinline__ float softplus1(float x) {
    float e = __expf(-fabsf(x));
    return fmaxf(x, 0.f) + 0.69314718055994531f * __log2f(1.f + e);
}
// tanh(x) = 1 - 2/(exp(2x)+1)
__device__ __forceinline__ float tanh1(float x) {
    float e = __expf(2.f * x);
    return 1.f - __fdividef(2.f, e + 1.f);
}

// ---------------- main persistent scan kernel (R11, unchanged) ---------------
__global__ void __launch_bounds__(NTHR, 1)
sde_scan_kernel(const float* __restrict__ init_noise, const float* __restrict__ dw_noise,
                const float* __restrict__ ts,   const float* __restrict__ embW,
                const float* __restrict__ embb, const float* __restrict__ fW1,
                const float* __restrict__ fb1,  const float* __restrict__ fW2,
                const float* __restrict__ fb2,  const float* __restrict__ fW3,
                const float* __restrict__ fb3,  const float* __restrict__ gW1,
                const float* __restrict__ gb1,  const float* __restrict__ gW2,
                const float* __restrict__ gb2,  const float* __restrict__ gW3,
                const float* __restrict__ gb3)
{
    extern __shared__ __align__(16) char smraw[];
    Smem& sm = *reinterpret_cast<Smem*>(smraw);
    const int tid = threadIdx.x;
    const int wg = tid & 127;            // layer neuron
    const int team = tid >> 7;           // 0,1
    const int p0 = 2 * team;             // team's pairs (ph1/ph2)
    const int rowbase = blockIdx.x * RROWS;

    // aliases over buffers that are dead during ph3/ph4
    float2 (*fo)[Ln]  = reinterpret_cast<float2(*)[Ln]>(&sm.h1f[0][0]);
    float2 (*geo)[Ln] = reinterpret_cast<float2(*)[Ln]>(&sm.h1g[0][0]);

    // ---- stage SMEM-resident weights (team-split) ----
    {
        const int j = wg;
        if (team == 0) {
#pragma unroll 4
            for (int k = 0; k < Ln; k++) sm.fW1t[j][k] = fW1[(k + 1) * Hn + j];
#pragma unroll 4
            for (int k = 0; k < Hn; k++) sm.fW2t[j][k] = fW2[k * Hn + j];
        } else {
#pragma unroll 4
            for (int k = 0; k < Ln; k++) sm.gW1t[j][k] = gW1[(k + 1) * Hn + j];
#pragma unroll 4
            for (int k = 0; k < Hn; k++) sm.gW2t[j][k] = gW2[k * Hn + j];
        }
    }

    // ---- per-thread register params ----
    const float w10f = __ldg(fW1 + wg), w10g = __ldg(gW1 + wg);
    const float bf1 = __ldg(fb1 + wg), bf2 = __ldg(fb2 + wg);
    const float bg1 = __ldg(gb1 + wg), bg2 = __ldg(gb2 + wg);
    const int l3 = tid & 63, q3 = tid >> 6;            // f3 mapping (4 pairs x 64 l)
    const float bf3v = __ldg(fb3 + l3);
    const float2 bg3v = *(const float2*)(gb3 + 2 * tid);  // outputs 2tid, 2tid+1

    // ---- z0 = init_noise @ emb_W + emb_b; store to zbuf[t=0] ----
    {
        int l = tid & 63, p = tid >> 6;
        float ax = __ldg(embb + l), ay = ax;
#pragma unroll 4
        for (int i = 0; i < DIn; i++) {
            float w = embW[i * Ln + l];
            ax = fmaf(init_noise[(rowbase + 2 * p) * DIn + i], w, ax);
            ay = fmaf(init_noise[(rowbase + 2 * p + 1) * DIn + i], w, ay);
        }
        sm.z2[p][l] = make_float2(ax, ay);
        zbuf[(size_t)blockIdx.x * (PAIRS * Ln) + tid] = *(const u64*)&sm.z2[p][l];
    }
    __syncthreads();

    // ---- 511 Euler-Maruyama steps, 4 barriers each --------------------------
    for (int s = 0; s < Tn - 1; s++) {
        const float tcur = __ldg(ts + s);
        const float dt = __ldg(ts + s + 1) - tcur;
        const float sq = sqrtf(dt);
        if (tid < 32) {   // Brownian increments (consumed in ph3, >=2 bars later)
            int p = tid >> 3, n = tid & 7;
            const float* dwp = dw_noise + ((size_t)s * Bn + rowbase + 2 * p) * Nn + n;
            sm.dws[p][n] = make_float2(dwp[0] * sq, dwp[Nn] * sq);
        }

        // ===== ph1: f layer1 + g layer1 (shared z2 act loads, 8 chains) =====
        {
            u64 z0 = dup2f(0.f);
            u64 fi = dup2f(fmaf(w10f, tcur, bf1));
            u64 gi = dup2f(fmaf(w10g, tcur, bg1));
            u64 fA[2] = { fi, fi }, fB[2] = { z0, z0 };
            u64 gA[2] = { gi, gi }, gB[2] = { z0, z0 };
#pragma unroll 4
            for (int c = 0; c < Ln / 4; c++) {
                float4 wf = *(const float4*)&sm.fW1t[wg][4 * c];
                float4 wgv = *(const float4*)&sm.gW1t[wg][4 * c];
                u64 f0 = dup2f(wf.x), f1 = dup2f(wf.y), f2 = dup2f(wf.z), f3 = dup2f(wf.w);
                u64 g0 = dup2f(wgv.x), g1 = dup2f(wgv.y), g2 = dup2f(wgv.z), g3 = dup2f(wgv.w);
#pragma unroll
                for (int e = 0; e < 2; e++) {
                    ulonglong2 x0 = *(const ulonglong2*)&sm.z2[p0 + e][4 * c];
                    ulonglong2 x1 = *(const ulonglong2*)&sm.z2[p0 + e][4 * c + 2];
                    fA[e] = f2fma(f0, x0.x, fA[e]);
                    fB[e] = f2fma(f1, x0.y, fB[e]);
                    fA[e] = f2fma(f2, x1.x, fA[e]);
                    fB[e] = f2fma(f3, x1.y, fB[e]);
                    gA[e] = f2fma(g0, x0.x, gA[e]);
                    gB[e] = f2fma(g1, x0.y, gB[e]);
                    gA[e] = f2fma(g2, x1.x, gA[e]);
                    gB[e] = f2fma(g3, x1.y, gB[e]);
                }
            }
#pragma unroll
            for (int e = 0; e < 2; e++) {
                u64 tf = f2add(fA[e], fB[e]);
                u64 tg = f2add(gA[e], gB[e]);
                float lo, hi;
                unpk2(tf, lo, hi);
                sm.h1f[p0 + e][wg] = make_float2(softplus1(lo), softplus1(hi));
                unpk2(tg, lo, hi);
                sm.h1g[p0 + e][wg] = make_float2(softplus1(lo), softplus1(hi));
            }
        }
        __syncthreads();

        // ===== ph2: f layer2 + g layer2 =====
        {
            u64 z0 = dup2f(0.f);
            u64 fi = dup2f(bf2), gi = dup2f(bg2);
            u64 fA[2] = { fi, fi }, fB[2] = { z0, z0 };
            u64 gA[2] = { gi, gi }, gB[2] = { z0, z0 };
#pragma unroll 4
            for (int c = 0; c < Hn / 4; c++) {
                float4 wf = *(const float4*)&sm.fW2t[wg][4 * c];
                float4 wgv = *(const float4*)&sm.gW2t[wg][4 * c];
                u64 f0 = dup2f(wf.x), f1 = dup2f(wf.y), f2 = dup2f(wf.z), f3 = dup2f(wf.w);
                u64 g0 = dup2f(wgv.x), g1 = dup2f(wgv.y), g2 = dup2f(wgv.z), g3 = dup2f(wgv.w);
#pragma unroll
                for (int e = 0; e < 2; e++) {
                    ulonglong2 xf0 = *(const ulonglong2*)&sm.h1f[p0 + e][4 * c];
                    ulonglong2 xf1 = *(const ulonglong2*)&sm.h1f[p0 + e][4 * c + 2];
                    fA[e] = f2fma(f0, xf0.x, fA[e]);
                    fB[e] = f2fma(f1, xf0.y, fB[e]);
                    fA[e] = f2fma(f2, xf1.x, fA[e]);
                    fB[e] = f2fma(f3, xf1.y, fB[e]);
                    ulonglong2 xg0 = *(const ulonglong2*)&sm.h1g[p0 + e][4 * c];
                    ulonglong2 xg1 = *(const ulonglong2*)&sm.h1g[p0 + e][4 * c + 2];
                    gA[e] = f2fma(g0, xg0.x, gA[e]);
                    gB[e] = f2fma(g1, xg0.y, gB[e]);
                    gA[e] = f2fma(g2, xg1.x, gA[e]);
                    gB[e] = f2fma(g3, xg1.y, gB[e]);
                }
            }
#pragma unroll
            for (int e = 0; e < 2; e++) {
                u64 tf = f2add(fA[e], fB[e]);
                u64 tg = f2add(gA[e], gB[e]);
                float lo, hi;
                unpk2(tf, lo, hi);
                sm.h2f[p0 + e][wg] = make_float2(softplus1(lo), softplus1(hi));
                unpk2(tg, lo, hi);
                sm.h2g[p0 + e][wg] = make_float2(softplus1(lo), softplus1(hi));
            }
        }
        __syncthreads();

        // ===== ph3: f3 (thread=(l3,q3)) fused with g3 (R8 schedule) =====
        {
            const u64 one2 = dup2f(1.f);
            u64 a0 = dup2f(bf3v), a1 = dup2f(0.f);
            const float* fp = fW3 + l3;
            u64 acc[PAIRS][2];
#pragma unroll
            for (int p = 0; p < PAIRS; p++) {
                acc[p][0] = dup2f(bg3v.x);
                acc[p][1] = dup2f(bg3v.y);
            }
            const float2* g2 = reinterpret_cast<const float2*>(gW3) + tid;
#pragma unroll 4
            for (int c = 0; c < Hn / 2; c++) {
                // f3: k = 2c, 2c+1
                u64 w0 = dup2f(__ldg(fp + (2 * c) * Ln));
                u64 w1 = dup2f(__ldg(fp + (2 * c + 1) * Ln));
                a0 = f2fma(w0, *(const u64*)&sm.h2f[q3][2 * c], a0);
                a1 = f2fma(w1, *(const u64*)&sm.h2f[q3][2 * c + 1], a1);
                // g3: k-rows 2c, 2c+1 (LDG.64, fully coalesced over warp)
                float2 va = __ldg(g2 + (size_t)(2 * c) * (Ln * Nn / 2));
                float2 vb = __ldg(g2 + (size_t)(2 * c + 1) * (Ln * Nn / 2));
                u64 wa0 = dup2f(va.x), wa1 = dup2f(va.y);
                u64 wb0 = dup2f(vb.x), wb1 = dup2f(vb.y);
#pragma unroll
                for (int p = 0; p < PAIRS; p++) {
                    ulonglong2 h = *(const ulonglong2*)&sm.h2g[p][2 * c];
                    acc[p][0] = f2fma(wa0, h.x, acc[p][0]);
                    acc[p][1] = f2fma(wa1, h.x, acc[p][1]);
                    acc[p][0] = f2fma(wb0, h.y, acc[p][0]);
                    acc[p][1] = f2fma(wb1, h.y, acc[p][1]);
                }
            }
            // f3 output -> fo (h1f alias; h1f dead this phase)
            {
                u64 t = f2add(a0, a1);
                float lo, hi; unpk2(t, lo, hi);
                fo[q3][l3] = make_float2(tanh1(lo), tanh1(hi));
            }
            // einsum: l = tid>>2, n's = (tid&3)*2, +1; reduce 4 lanes via shfl
            const int l = tid >> 2, nb = (tid & 3) * 2;
#pragma unroll
            for (int p = 0; p < PAIRS; p++) {
                float x0, x1, y0, y1;
                unpk2(acc[p][0], x0, x1);
                unpk2(acc[p][1], y0, y1);
                u64 t0 = pk2(tanh1(x0), tanh1(x1));
                u64 t1 = pk2(tanh1(y0), tanh1(y1));
                u64 pa = f2fma(t0, *(const u64*)&sm.dws[p][nb], dup2f(0.f));
                pa = f2fma(t1, *(const u64*)&sm.dws[p][nb + 1], pa);
                pa = f2fma(one2, __shfl_xor_sync(0xffffffffu, pa, 1), pa);
                pa = f2fma(one2, __shfl_xor_sync(0xffffffffu, pa, 2), pa);
                if ((tid & 3) == 0) *(u64*)&geo[p][l] = pa;
            }
        }
        __syncthreads();

        // ===== ph4: z update (thread = (p,l)) + stream z to global =====
        {
            int l = tid & 63, p = tid >> 6;
            const u64 one2 = dup2f(1.f);
            u64 dt2 = dup2f(dt);
            u64 z = *(const u64*)&sm.z2[p][l];
            z = f2fma(*(const u64*)&fo[p][l], dt2, z);
            z = f2fma(one2, *(const u64*)&geo[p][l], z);
            *(u64*)&sm.z2[p][l] = z;
            zbuf[((size_t)(s + 1) * NCTA + blockIdx.x) * (PAIRS * Ln) + tid] = z;
        }
        __syncthreads();
    }
}

// ---------------- readout kernel: x = relu(z@rW1+b1)@rW2+b2 ------------------
// Four time steps per iteration: weights loaded once serve 4x the FMA work;
// barriers amortized 4x.
#define RO_TS 32   /* time steps per block */
#define TS4 4      /* time steps per iteration */
struct __align__(16) RoSmem {
    float rw1t[Hn][68];          // rW1 transposed [j][l]
    float w2t[DOn][130];         // rW2 transposed [d][k], pad 130
    float2 zt[TS4][PAIRS][Ln];   // four z tiles (8 KB)
    float h1T[TS4][RROWS][132];  // stage-1 outputs (16.9 KB)
};

__global__ void __launch_bounds__(256, 3)
readout_kernel(const float* __restrict__ rW1, const float* __restrict__ rb1,
               const float* __restrict__ rW2, const float* __restrict__ rb2,
               float* __restrict__ out)
{
    extern __shared__ __align__(16) char smraw[];
    RoSmem& sm = *reinterpret_cast<RoSmem*>(smraw);
    const int tid = threadIdx.x;
    const int cta = blockIdx.x & (NCTA - 1);
    const int slice = blockIdx.x >> 7;
    const int rowbase = cta * RROWS;

    // stage rW1 transposed: [j][l], coalesced LDG over j
    {
        const int jj = tid & 127, half = tid >> 7;
#pragma unroll 4
        for (int l = half * 32; l < half * 32 + 32; l++)
            sm.rw1t[jj][l] = rW1[l * Hn + jj];
    }
    // stage rW2 transposed: [d][k]
    for (int i = tid; i < Hn * DOn; i += 256) {
        int d = i & 15, k = i >> 4;
        sm.w2t[d][k] = rW2[i];
    }
    const float rb1v = __ldg(rb1 + (tid & 127));
    const int jr = tid & 127, p0 = (tid >> 7) * 2;             // stage-1 mapping
    const int row2 = tid >> 5, kh5 = (tid >> 4) & 1, d5 = tid & 15;  // stage-2
    const float rb2v = __ldg(rb2 + d5);
    __syncthreads();

    for (int it = 0; it < RO_TS / TS4; it++) {
        const int t0 = slice * RO_TS + TS4 * it;
        // load all TS4 z tiles (coalesced u64 per thread per tile)
        {
            size_t base = ((size_t)t0 * NCTA + cta) * (PAIRS * Ln);
#pragma unroll
            for (int tt = 0; tt < TS4; tt++)
                ((u64*)&sm.zt[tt][0][0])[tid] =
                    zbuf[base + (size_t)tt * NCTA * (PAIRS * Ln) + tid];
        }
        __syncthreads();
        // stage 1: h = relu(z @ rW1 + b1) for all TS4 t; thread = (jr, 2 pairs)
        {
            u64 aA[TS4][2], aB[TS4][2];
            u64 bi = dup2f(rb1v), z0 = dup2f(0.f);
#pragma unroll
            for (int tt = 0; tt < TS4; tt++) {
                aA[tt][0] = bi; aA[tt][1] = bi;
                aB[tt][0] = z0; aB[tt][1] = z0;
            }
#pragma unroll 4
            for (int c = 0; c < Ln / 4; c++) {
                float4 w = *(const float4*)&sm.rw1t[jr][4 * c];
                u64 w0 = dup2f(w.x), w1 = dup2f(w.y), w2 = dup2f(w.z), w3 = dup2f(w.w);
#pragma unroll
                for (int tt = 0; tt < TS4; tt++) {
#pragma unroll
                    for (int e = 0; e < 2; e++) {
                        ulonglong2 x0 = *(const ulonglong2*)&sm.zt[tt][p0 + e][4 * c];
                        ulonglong2 x1 = *(const ulonglong2*)&sm.zt[tt][p0 + e][4 * c + 2];
                        aA[tt][e] = f2fma(w0, x0.x, aA[tt][e]);
                        aB[tt][e] = f2fma(w1, x0.y, aB[tt][e]);
                        aA[tt][e] = f2fma(w2, x1.x, aA[tt][e]);
                        aB[tt][e] = f2fma(w3, x1.y, aB[tt][e]);
                    }
                }
            }
#pragma unroll
            for (int tt = 0; tt < TS4; tt++)
#pragma unroll
                for (int e = 0; e < 2; e++) {
                    u64 tv = f2add(aA[tt][e], aB[tt][e]);
                    float lo, hi; unpk2(tv, lo, hi);
                    sm.h1T[tt][2 * (p0 + e)][jr]     = fmaxf(lo, 0.f);
                    sm.h1T[tt][2 * (p0 + e) + 1][jr] = fmaxf(hi, 0.f);
                }
        }
        __syncthreads();
        // stage 2: x = h @ rW2 + b2 for all TS4 t; thread = (row2, kh5, d5)
        {
            u64 acc[TS4];
#pragma unroll
            for (int tt = 0; tt < TS4; tt++) acc[tt] = dup2f(0.f);
            const float* wT = &sm.w2t[d5][kh5 * 64];
#pragma unroll 8
            for (int kk = 0; kk < 64; kk += 2) {
                u64 wv = *(const u64*)&wT[kk];
#pragma unroll
                for (int tt = 0; tt < TS4; tt++)
                    acc[tt] = f2fma(*(const u64*)&sm.h1T[tt][row2][kh5 * 64 + kk],
                                    wv, acc[tt]);
            }
            float av[TS4];
#pragma unroll
            for (int tt = 0; tt < TS4; tt++) {
                float lo, hi; unpk2(acc[tt], lo, hi);
                av[tt] = lo + hi;
                av[tt] += __shfl_xor_sync(0xffffffffu, av[tt], 16);
            }
            if (kh5 == 0) {
                size_t row = (size_t)rowbase + row2;
#pragma unroll
                for (int tt = 0; tt < TS4; tt++) {
                    float a = av[tt] + rb2v;
                    int t = t0 + tt;
                    out[(row * Tn + t) * DOn + d5] = a;
                    if ((t & 7) == 0)
                        out[XFULL + (row * (Tn / 8) + (t >> 3)) * DOn + d5] = a;
                }
            }
        }
        __syncthreads();
    }
}

extern "C" void kernel_launch(void* const* d_in, const int* in_sizes, int n_in,
                              void* d_out, int out_size) {
    (void)in_sizes; (void)n_in; (void)out_size;
    cudaFuncSetAttribute(sde_scan_kernel, cudaFuncAttributeMaxDynamicSharedMemorySize,
                         (int)sizeof(Smem));
    cudaFuncSetAttribute(readout_kernel, cudaFuncAttributeMaxDynamicSharedMemorySize,
                         (int)sizeof(RoSmem));
    sde_scan_kernel<<<NCTA, NTHR, sizeof(Smem)>>>(
        (const float*)d_in[0],  (const float*)d_in[1],  (const float*)d_in[2],
        (const float*)d_in[3],  (const float*)d_in[4],  (const float*)d_in[5],
        (const float*)d_in[6],  (const float*)d_in[7],  (const float*)d_in[8],
        (const float*)d_in[9],  (const float*)d_in[10], (const float*)d_in[11],
        (const float*)d_in[12], (const float*)d_in[13], (const float*)d_in[14],
        (const float*)d_in[15], (const float*)d_in[16]);
    readout_kernel<<<NCTA * (Tn / RO_TS), 256, sizeof(RoSmem)>>>(
        (const float*)d_in[17], (const float*)d_in[18],
        (const float*)d_in[19], (const float*)d_in[20],
        (float*)d_out);
}